// round 4
// baseline (speedup 1.0000x reference)
#include <cuda_runtime.h>

#define NN    50000
#define EE    1600000
#define EPSB  1e-5f
#define NBLK  148
#define T     256
#define CHUNK 338          // ceil(NN/NBLK)
#define KCH   10811        // ceil(NN*32/NBLK)

// -------- static device scratch --------
__device__ int2  g_edge[EE];     // CSR: (src, weight bits)
__device__ int   g_deg[NN];
__device__ float g_dinv[NN];
__device__ int   g_ptr[NN + 1];
__device__ int   g_pos[NN];
__device__ int   g_part[NBLK];
__device__ float g_xw[NN * 32];
__device__ float g_y [NN * 32];
__device__ float g_ssum[3 * 32];
__device__ float g_ssq [3 * 32];
__device__ float g_fc0[128];
__device__ unsigned g_cnt_bar = 0;
__device__ volatile unsigned g_gen = 0;

static __device__ __forceinline__ float lrelu(float v) {
    return v > 0.f ? v : 0.1f * v;
}

// software grid barrier: all NBLK blocks resident (grid == 148 <= SM count)
static __device__ __forceinline__ void gridbar() {
    __syncthreads();
    if (threadIdx.x == 0) {
        __threadfence();
        unsigned gen = g_gen;
        if (atomicAdd(&g_cnt_bar, 1u) == NBLK - 1) {
            g_cnt_bar = 0;
            __threadfence();
            g_gen = gen + 1;
        } else {
            while (g_gen == gen) __nanosleep(64);
        }
        __threadfence();
    }
    __syncthreads();
}

__global__ __launch_bounds__(T) void k_mega(
    const void* ei, const float* __restrict__ emb,
    const float* __restrict__ cW0, const float* __restrict__ cb0,
    const float* __restrict__ gg0, const float* __restrict__ bt0,
    const float* __restrict__ cW1, const float* __restrict__ cb1,
    const float* __restrict__ gg1, const float* __restrict__ bt1,
    const float* __restrict__ cW2, const float* __restrict__ cb2,
    const float* __restrict__ gg2, const float* __restrict__ bt2,
    const float* __restrict__ fW0, const float* __restrict__ fb0,
    const float* __restrict__ fW1, const float* __restrict__ fb1,
    const float* __restrict__ fW2, const float* __restrict__ fb2,
    const float* __restrict__ fW3, const float* __restrict__ fb3,
    float* __restrict__ out)
{
    __shared__ float s_W[4096];          // 16 KB: weights / stats scratch / fc buffers
    __shared__ int   s_loc[CHUNK + 2];   // local scan offsets (persist across barrier)
    __shared__ int   s_scan[256];
    __shared__ float s_bnA[32], s_bnB[32];
    __shared__ int   s_wsum[8];
    __shared__ int   s_is64;

    const int b = blockIdx.x, t = threadIdx.x;
    const int wid = t >> 5, lane = t & 31;

    // ---- phase 0: init + dtype detect ----
    if (t == 0) {
        const unsigned* w = (const unsigned*)ei;
        int nz = 0;
        for (int i = 0; i < 64; i++) nz += (w[2 * i + 1] != 0u);
        s_is64 = (nz == 0);
    }
    for (int i = b * T + t; i < NN; i += NBLK * T) g_deg[i] = 0;
    if (b == 0) {
        if (t < 96) { g_ssum[t] = 0.f; g_ssq[t] = 0.f; }
        if (t < 128) g_fc0[t] = 0.f;
    }
    __syncthreads();
    const int is64 = s_is64;
    gridbar();  // B1

    // ---- phase 1: degree histogram ----
    if (is64) {
        const long long* p = (const long long*)ei;
        for (int e = b * T + t; e < EE; e += NBLK * T)
            atomicAdd(&g_deg[(int)p[EE + e]], 1);
    } else {
        const int* p = (const int*)ei;
        for (int e = b * T + t; e < EE; e += NBLK * T)
            atomicAdd(&g_deg[p[EE + e]], 1);
    }
    gridbar();  // B2

    // ---- phase 2a: per-block local exclusive scan + dinv ----
    {
        int base = b * CHUNK;
        int cnt = NN - base; if (cnt > CHUNK) cnt = CHUNK; if (cnt < 0) cnt = 0;
        int i0 = 2 * t, i1 = 2 * t + 1;
        int v0 = (i0 < cnt) ? g_deg[base + i0] : 0;
        int v1 = (i1 < cnt) ? g_deg[base + i1] : 0;
        if (i0 < cnt) g_dinv[base + i0] = rsqrtf((float)v0 + 2.f);
        if (i1 < cnt) g_dinv[base + i1] = rsqrtf((float)v1 + 2.f);
        int pair = v0 + v1;
        int incl = pair;
#pragma unroll
        for (int off = 1; off < 32; off <<= 1) {
            int u = __shfl_up_sync(0xffffffffu, incl, off);
            if (lane >= off) incl += u;
        }
        if (lane == 31) s_wsum[wid] = incl;
        __syncthreads();
        if (t == 0) {
            int acc = 0;
            for (int w8 = 0; w8 < 8; w8++) { int s = s_wsum[w8]; s_wsum[w8] = acc; acc += s; }
            g_part[b] = acc;  // block total
        }
        __syncthreads();
        int excl = s_wsum[wid] + incl - pair;
        if (i0 < cnt) s_loc[i0] = excl;
        if (i1 < cnt) s_loc[i1] = excl + v0;
    }
    gridbar();  // B3

    // ---- phase 2b: block 0 scans partials ----
    if (b == 0) {
        int v = (t < NBLK) ? g_part[t] : 0;
        s_scan[t] = v;
        __syncthreads();
#pragma unroll
        for (int off = 1; off < 256; off <<= 1) {
            int u = (t >= off) ? s_scan[t - off] : 0;
            __syncthreads();
            s_scan[t] += u;
            __syncthreads();
        }
        if (t < NBLK) g_part[t] = s_scan[t] - v;  // exclusive
        if (t == 0) g_ptr[NN] = EE;
    }
    gridbar();  // B4

    // ---- phase 2c: emit ptr/pos ----
    {
        int base = b * CHUNK;
        int cnt = NN - base; if (cnt > CHUNK) cnt = CHUNK; if (cnt < 0) cnt = 0;
        int off = g_part[b];
        for (int i = t; i < cnt; i += T) {
            int val = off + s_loc[i];
            g_ptr[base + i] = val;
            g_pos[base + i] = val;
        }
    }
    gridbar();  // B5

    // ---- phase 3: CSR placement ----
    if (is64) {
        const long long* p = (const long long*)ei;
        for (int e = b * T + t; e < EE; e += NBLK * T) {
            int r = (int)p[e], c = (int)p[EE + e];
            int slot = atomicAdd(&g_pos[c], 1);
            g_edge[slot] = make_int2(r, __float_as_int(g_dinv[r] * g_dinv[c]));
        }
    } else {
        const int* p = (const int*)ei;
        for (int e = b * T + t; e < EE; e += NBLK * T) {
            int r = p[e], c = p[EE + e];
            int slot = atomicAdd(&g_pos[c], 1);
            g_edge[slot] = make_int2(r, __float_as_int(g_dinv[r] * g_dinv[c]));
        }
    }
    gridbar();  // B6

    // ---- 3 GCN layers ----
    const float* cWs[3] = {cW0, cW1, cW2};
    const float* cbs[3] = {cb0, cb1, cb2};
    const float* ggs[3] = {gg0, gg1, gg2};
    const float* bts[3] = {bt0, bt1, bt2};

    for (int l = 0; l < 3; l++) {
        // --- xw = BN(x) @ W, warp per node ---
        int cin = (l == 0) ? 128 : 32;
        const float* W = cWs[l];
        for (int i = t; i < cin * 32; i += T) s_W[i] = W[i];
        if (l > 0 && t < 32) {
            float sum = g_ssum[(l - 1) * 32 + t], sq = g_ssq[(l - 1) * 32 + t];
            float mean = sum / (float)NN;
            float var = sq / (float)NN - mean * mean;
            float a = ggs[l - 1][t] * rsqrtf(var + EPSB);
            s_bnA[t] = a; s_bnB[t] = bts[l - 1][t] - mean * a;
        }
        __syncthreads();
        if (l == 0) {
            for (int node = b * 8 + wid; node < NN; node += NBLK * 8) {
                const float* xr = emb + (size_t)node * 128;
                float v0 = xr[lane], v1 = xr[lane + 32], v2 = xr[lane + 64], v3 = xr[lane + 96];
                float acc = 0.f;
#pragma unroll
                for (int k = 0; k < 32; k++) acc += __shfl_sync(0xffffffffu, v0, k) * s_W[k * 32 + lane];
#pragma unroll
                for (int k = 0; k < 32; k++) acc += __shfl_sync(0xffffffffu, v1, k) * s_W[(k + 32) * 32 + lane];
#pragma unroll
                for (int k = 0; k < 32; k++) acc += __shfl_sync(0xffffffffu, v2, k) * s_W[(k + 64) * 32 + lane];
#pragma unroll
                for (int k = 0; k < 32; k++) acc += __shfl_sync(0xffffffffu, v3, k) * s_W[(k + 96) * 32 + lane];
                g_xw[node * 32 + lane] = acc;
            }
        } else {
            for (int node = b * 8 + wid; node < NN; node += NBLK * 8) {
                float v = g_y[node * 32 + lane] * s_bnA[lane] + s_bnB[lane];
                float acc = 0.f;
#pragma unroll
                for (int k = 0; k < 32; k++) acc += __shfl_sync(0xffffffffu, v, k) * s_W[k * 32 + lane];
                g_xw[node * 32 + lane] = acc;
            }
        }
        gridbar();

        // --- gather + self loop + bias + lrelu + FUSED BN stats ---
        {
            const float4* xw4 = (const float4*)g_xw;
            const float* bb = cbs[l];
            int q = t & 7;   // fixed: stride NBLK*T is a multiple of 8
            float b0 = bb[q * 4 + 0], b1 = bb[q * 4 + 1], b2 = bb[q * 4 + 2], b3 = bb[q * 4 + 3];
            float ss0 = 0, ss1 = 0, ss2 = 0, ss3 = 0;
            float sq0 = 0, sq1 = 0, sq2 = 0, sq3 = 0;
            for (int unit = b * T + t; unit < NN * 8; unit += NBLK * T) {
                int node = unit >> 3;
                float di = g_dinv[node];
                float sw = 2.f * di * di;
                float4 self = xw4[node * 8 + q];
                float ax = self.x * sw + b0, ay = self.y * sw + b1;
                float az = self.z * sw + b2, aw = self.w * sw + b3;
                int s = g_ptr[node], e = g_ptr[node + 1];
                int i = s;
                for (; i + 3 < e; i += 4) {
                    int2 e0 = __ldg(&g_edge[i]),     e1 = __ldg(&g_edge[i + 1]);
                    int2 e2 = __ldg(&g_edge[i + 2]), e3 = __ldg(&g_edge[i + 3]);
                    float4 u0 = xw4[e0.x * 8 + q], u1 = xw4[e1.x * 8 + q];
                    float4 u2 = xw4[e2.x * 8 + q], u3 = xw4[e3.x * 8 + q];
                    float w0 = __int_as_float(e0.y), w1 = __int_as_float(e1.y);
                    float w2 = __int_as_float(e2.y), w3 = __int_as_float(e3.y);
                    ax += w0 * u0.x + w1 * u1.x + w2 * u2.x + w3 * u3.x;
                    ay += w0 * u0.y + w1 * u1.y + w2 * u2.y + w3 * u3.y;
                    az += w0 * u0.z + w1 * u1.z + w2 * u2.z + w3 * u3.z;
                    aw += w0 * u0.w + w1 * u1.w + w2 * u2.w + w3 * u3.w;
                }
                for (; i < e; i++) {
                    int2 e0 = __ldg(&g_edge[i]);
                    float w0 = __int_as_float(e0.y);
                    float4 u0 = xw4[e0.x * 8 + q];
                    ax += w0 * u0.x; ay += w0 * u0.y; az += w0 * u0.z; aw += w0 * u0.w;
                }
                ax = lrelu(ax); ay = lrelu(ay); az = lrelu(az); aw = lrelu(aw);
                ((float4*)g_y)[node * 8 + q] = make_float4(ax, ay, az, aw);
                ss0 += ax; ss1 += ay; ss2 += az; ss3 += aw;
                sq0 += ax * ax; sq1 += ay * ay; sq2 += az * az; sq3 += aw * aw;
            }
            __syncthreads();  // s_W (weights) free now — reuse as stats scratch
            s_W[t * 4 + 0] = ss0; s_W[t * 4 + 1] = ss1; s_W[t * 4 + 2] = ss2; s_W[t * 4 + 3] = ss3;
            s_W[1024 + t * 4 + 0] = sq0; s_W[1024 + t * 4 + 1] = sq1;
            s_W[1024 + t * 4 + 2] = sq2; s_W[1024 + t * 4 + 3] = sq3;
            __syncthreads();
            if (t < 32) {   // channel c = t; contributors tt with tt&7 == t>>2, component t&3
                int qq = t >> 2, comp = t & 3;
                float S = 0.f, Q = 0.f;
#pragma unroll
                for (int m = 0; m < 32; m++) {
                    int tt = qq + 8 * m;
                    S += s_W[tt * 4 + comp];
                    Q += s_W[1024 + tt * 4 + comp];
                }
                atomicAdd(&g_ssum[l * 32 + t], S);
                atomicAdd(&g_ssq [l * 32 + t], Q);
            }
        }
        gridbar();
    }

    // ---- FC0: warp-per-k-row streaming of fW0 (819 MB), BN fold inline ----
    {
        if (t < 32) {
            float sum = g_ssum[2 * 32 + t], sq = g_ssq[2 * 32 + t];
            float mean = sum / (float)NN;
            float var = sq / (float)NN - mean * mean;
            float a = gg2[t] * rsqrtf(var + EPSB);
            s_bnA[t] = a; s_bnB[t] = bt2[t] - mean * a;
        }
        __syncthreads();
        int start = b * KCH;
        int end = start + KCH; if (end > NN * 32) end = NN * 32;
        float a0 = 0.f, a1 = 0.f, a2 = 0.f, a3 = 0.f;
#pragma unroll 4
        for (int k = start + wid; k < end; k += 8) {
            float xk = g_y[k] * s_bnA[k & 31] + s_bnB[k & 31];
            float4 wv = *(const float4*)(fW0 + (size_t)k * 128 + 4 * lane);
            a0 += xk * wv.x; a1 += xk * wv.y; a2 += xk * wv.z; a3 += xk * wv.w;
        }
        __syncthreads();
        s_W[wid * 128 + 4 * lane + 0] = a0;
        s_W[wid * 128 + 4 * lane + 1] = a1;
        s_W[wid * 128 + 4 * lane + 2] = a2;
        s_W[wid * 128 + 4 * lane + 3] = a3;
        __syncthreads();
        if (t < 128) {
            float s = 0.f;
#pragma unroll
            for (int w8 = 0; w8 < 8; w8++) s += s_W[w8 * 128 + t];
            atomicAdd(&g_fc0[t], s);
        }
    }
    gridbar();  // final: g_fc0 complete

    // ---- FC tail (block 0) ----
    if (b == 0) {
        if (t < 128) s_W[t] = lrelu(g_fc0[t] + fb0[t]);
        __syncthreads();
        if (t < 64) {
            float a = fb1[t];
#pragma unroll 8
            for (int k = 0; k < 128; k++) a += s_W[k] * fW1[k * 64 + t];
            s_W[256 + t] = lrelu(a);
        }
        __syncthreads();
        if (t < 32) {
            float a = fb2[t];
#pragma unroll 8
            for (int k = 0; k < 64; k++) a += s_W[256 + k] * fW2[k * 32 + t];
            s_W[384 + t] = lrelu(a);
        }
        __syncthreads();
        if (t == 0) {
            float a = fb3[0];
#pragma unroll
            for (int k = 0; k < 32; k++) a += s_W[384 + k] * fW3[k];
            out[0] = a;
        }
    }
}

extern "C" void kernel_launch(void* const* d_in, const int* in_sizes, int n_in,
                              void* d_out, int out_size) {
    k_mega<<<NBLK, T>>>(
        d_in[0], (const float*)d_in[1],
        (const float*)d_in[2],  (const float*)d_in[3],  (const float*)d_in[4],  (const float*)d_in[5],
        (const float*)d_in[6],  (const float*)d_in[7],  (const float*)d_in[8],  (const float*)d_in[9],
        (const float*)d_in[10], (const float*)d_in[11], (const float*)d_in[12], (const float*)d_in[13],
        (const float*)d_in[14], (const float*)d_in[15], (const float*)d_in[16], (const float*)d_in[17],
        (const float*)d_in[18], (const float*)d_in[19], (const float*)d_in[20], (const float*)d_in[21],
        (float*)d_out);
    (void)in_sizes; (void)n_in; (void)out_size;
}

// round 5
// speedup vs baseline: 1.3709x; 1.3709x over previous
#include <cuda_runtime.h>

#define NN    50000
#define EE    1600000
#define EPSB  1e-5f
#define NBLK  148
#define T     1024
#define CHUNK 338          // ceil(NN/NBLK)
#define KCH   10811        // ceil(NN*32/NBLK)

// -------- static device scratch --------
__device__ int2  g_edge[EE];     // CSR: (src, weight bits)
__device__ int   g_deg[NN];
__device__ float g_dinv[NN];
__device__ int   g_ptr[NN + 1];
__device__ int   g_pos[NN];
__device__ int   g_part[NBLK];
__device__ float g_xw[NN * 32];
__device__ float g_y [NN * 32];
__device__ float g_ssum[3 * 32];
__device__ float g_ssq [3 * 32];
__device__ float g_fc0[128];
__device__ unsigned g_cnt_bar = 0;
__device__ volatile unsigned g_gen = 0;

static __device__ __forceinline__ float lrelu(float v) {
    return v > 0.f ? v : 0.1f * v;
}

// software grid barrier: all NBLK blocks resident (grid == 148 <= SM count)
static __device__ __forceinline__ void gridbar() {
    __syncthreads();
    if (threadIdx.x == 0) {
        __threadfence();
        unsigned gen = g_gen;
        if (atomicAdd(&g_cnt_bar, 1u) == NBLK - 1) {
            g_cnt_bar = 0;
            __threadfence();
            g_gen = gen + 1;
        } else {
            while (g_gen == gen) __nanosleep(64);
        }
        __threadfence();
    }
    __syncthreads();
}

__global__ __launch_bounds__(T, 1) void k_mega(
    const void* ei, const float* __restrict__ emb,
    const float* __restrict__ cW0, const float* __restrict__ cb0,
    const float* __restrict__ gg0, const float* __restrict__ bt0,
    const float* __restrict__ cW1, const float* __restrict__ cb1,
    const float* __restrict__ gg1, const float* __restrict__ bt1,
    const float* __restrict__ cW2, const float* __restrict__ cb2,
    const float* __restrict__ gg2, const float* __restrict__ bt2,
    const float* __restrict__ fW0, const float* __restrict__ fb0,
    const float* __restrict__ fW1, const float* __restrict__ fb1,
    const float* __restrict__ fW2, const float* __restrict__ fb2,
    const float* __restrict__ fW3, const float* __restrict__ fb3,
    float* __restrict__ out)
{
    __shared__ float s_W[8192];          // 32 KB: weights / stats scratch / fc buffers
    __shared__ int   s_loc[CHUNK + 2];   // local scan offsets (persist across barrier)
    __shared__ int   s_scan[256];
    __shared__ float s_bnA[32], s_bnB[32];
    __shared__ int   s_wsum[32];
    __shared__ int   s_is64;

    const int b = blockIdx.x, t = threadIdx.x;
    const int wid = t >> 5, lane = t & 31;

    // ---- phase 0: init + dtype detect ----
    if (t == 0) {
        const unsigned* w = (const unsigned*)ei;
        int nz = 0;
        for (int i = 0; i < 64; i++) nz += (w[2 * i + 1] != 0u);
        s_is64 = (nz == 0);
    }
    for (int i = b * T + t; i < NN; i += NBLK * T) g_deg[i] = 0;
    if (b == 0) {
        if (t < 96) { g_ssum[t] = 0.f; g_ssq[t] = 0.f; }
        if (t < 128) g_fc0[t] = 0.f;
    }
    __syncthreads();
    const int is64 = s_is64;
    gridbar();  // B1

    // ---- phase 1: degree histogram ----
    if (is64) {
        const long long* p = (const long long*)ei;
        for (int e = b * T + t; e < EE; e += NBLK * T)
            atomicAdd(&g_deg[(int)p[EE + e]], 1);
    } else {
        const int* p = (const int*)ei;
        for (int e = b * T + t; e < EE; e += NBLK * T)
            atomicAdd(&g_deg[p[EE + e]], 1);
    }
    gridbar();  // B2

    // ---- phase 2a: per-block local exclusive scan + dinv (1 elem/thread) ----
    {
        int base = b * CHUNK;
        int cnt = NN - base; if (cnt > CHUNK) cnt = CHUNK; if (cnt < 0) cnt = 0;
        int v = (t < cnt) ? g_deg[base + t] : 0;
        if (t < cnt) g_dinv[base + t] = rsqrtf((float)v + 2.f);
        int incl = v;
#pragma unroll
        for (int off = 1; off < 32; off <<= 1) {
            int u = __shfl_up_sync(0xffffffffu, incl, off);
            if (lane >= off) incl += u;
        }
        if (lane == 31) s_wsum[wid] = incl;
        __syncthreads();
        if (wid == 0) {
            int wv = s_wsum[lane];
            int winc = wv;
#pragma unroll
            for (int off = 1; off < 32; off <<= 1) {
                int u = __shfl_up_sync(0xffffffffu, winc, off);
                if (lane >= off) winc += u;
            }
            s_wsum[lane] = winc - wv;          // exclusive warp offsets
            if (lane == 31) g_part[b] = winc;  // block total
        }
        __syncthreads();
        int excl = s_wsum[wid] + incl - v;
        if (t < cnt) s_loc[t] = excl;
    }
    gridbar();  // B3

    // ---- phase 2b: block 0 scans partials (guarded Hillis-Steele, 256 wide) ----
    if (b == 0) {
        int v = (t < NBLK) ? g_part[t] : 0;
        if (t < 256) s_scan[t] = v;
        __syncthreads();
#pragma unroll
        for (int off = 1; off < 256; off <<= 1) {
            int u = (t >= off && t < 256) ? s_scan[t - off] : 0;
            __syncthreads();
            if (t < 256) s_scan[t] += u;
            __syncthreads();
        }
        if (t < NBLK) g_part[t] = s_scan[t] - v;  // exclusive
        if (t == 0) g_ptr[NN] = EE;
    }
    gridbar();  // B4

    // ---- phase 2c: emit ptr/pos ----
    {
        int base = b * CHUNK;
        int cnt = NN - base; if (cnt > CHUNK) cnt = CHUNK; if (cnt < 0) cnt = 0;
        int off = g_part[b];
        if (t < cnt) {
            int val = off + s_loc[t];
            g_ptr[base + t] = val;
            g_pos[base + t] = val;
        }
    }
    gridbar();  // B5

    // ---- phase 3: CSR placement ----
    if (is64) {
        const long long* p = (const long long*)ei;
        for (int e = b * T + t; e < EE; e += NBLK * T) {
            int r = (int)p[e], c = (int)p[EE + e];
            int slot = atomicAdd(&g_pos[c], 1);
            g_edge[slot] = make_int2(r, __float_as_int(g_dinv[r] * g_dinv[c]));
        }
    } else {
        const int* p = (const int*)ei;
        for (int e = b * T + t; e < EE; e += NBLK * T) {
            int r = p[e], c = p[EE + e];
            int slot = atomicAdd(&g_pos[c], 1);
            g_edge[slot] = make_int2(r, __float_as_int(g_dinv[r] * g_dinv[c]));
        }
    }
    gridbar();  // B6

    // ---- 3 GCN layers ----
    const float* cWs[3] = {cW0, cW1, cW2};
    const float* cbs[3] = {cb0, cb1, cb2};
    const float* ggs[3] = {gg0, gg1, gg2};
    const float* bts[3] = {bt0, bt1, bt2};

    for (int l = 0; l < 3; l++) {
        // --- xw = BN(x) @ W, warp per node (32 warps/block) ---
        int cin = (l == 0) ? 128 : 32;
        const float* W = cWs[l];
        for (int i = t; i < cin * 32; i += T) s_W[i] = W[i];
        if (l > 0 && t < 32) {
            float sum = g_ssum[(l - 1) * 32 + t], sq = g_ssq[(l - 1) * 32 + t];
            float mean = sum / (float)NN;
            float var = sq / (float)NN - mean * mean;
            float a = ggs[l - 1][t] * rsqrtf(var + EPSB);
            s_bnA[t] = a; s_bnB[t] = bts[l - 1][t] - mean * a;
        }
        __syncthreads();
        if (l == 0) {
            for (int node = b * 32 + wid; node < NN; node += NBLK * 32) {
                const float* xr = emb + (size_t)node * 128;
                float v0 = xr[lane], v1 = xr[lane + 32], v2 = xr[lane + 64], v3 = xr[lane + 96];
                float acc = 0.f;
#pragma unroll
                for (int k = 0; k < 32; k++) acc += __shfl_sync(0xffffffffu, v0, k) * s_W[k * 32 + lane];
#pragma unroll
                for (int k = 0; k < 32; k++) acc += __shfl_sync(0xffffffffu, v1, k) * s_W[(k + 32) * 32 + lane];
#pragma unroll
                for (int k = 0; k < 32; k++) acc += __shfl_sync(0xffffffffu, v2, k) * s_W[(k + 64) * 32 + lane];
#pragma unroll
                for (int k = 0; k < 32; k++) acc += __shfl_sync(0xffffffffu, v3, k) * s_W[(k + 96) * 32 + lane];
                g_xw[node * 32 + lane] = acc;
            }
        } else {
            for (int node = b * 32 + wid; node < NN; node += NBLK * 32) {
                float v = g_y[node * 32 + lane] * s_bnA[lane] + s_bnB[lane];
                float acc = 0.f;
#pragma unroll
                for (int k = 0; k < 32; k++) acc += __shfl_sync(0xffffffffu, v, k) * s_W[k * 32 + lane];
                g_xw[node * 32 + lane] = acc;
            }
        }
        gridbar();

        // --- gather + self loop + bias + lrelu + FUSED BN stats ---
        {
            const float4* xw4 = (const float4*)g_xw;
            const float* bb = cbs[l];
            int q = t & 7;   // fixed: stride NBLK*T is a multiple of 8
            float b0 = bb[q * 4 + 0], b1 = bb[q * 4 + 1], b2 = bb[q * 4 + 2], b3 = bb[q * 4 + 3];
            float ss0 = 0, ss1 = 0, ss2 = 0, ss3 = 0;
            float sq0 = 0, sq1 = 0, sq2 = 0, sq3 = 0;
            for (int unit = b * T + t; unit < NN * 8; unit += NBLK * T) {
                int node = unit >> 3;
                float di = g_dinv[node];
                float sw = 2.f * di * di;
                float4 self = xw4[node * 8 + q];
                float ax = self.x * sw + b0, ay = self.y * sw + b1;
                float az = self.z * sw + b2, aw = self.w * sw + b3;
                int s = g_ptr[node], e = g_ptr[node + 1];
                int i = s;
                for (; i + 3 < e; i += 4) {
                    int2 e0 = __ldg(&g_edge[i]),     e1 = __ldg(&g_edge[i + 1]);
                    int2 e2 = __ldg(&g_edge[i + 2]), e3 = __ldg(&g_edge[i + 3]);
                    float4 u0 = xw4[e0.x * 8 + q], u1 = xw4[e1.x * 8 + q];
                    float4 u2 = xw4[e2.x * 8 + q], u3 = xw4[e3.x * 8 + q];
                    float w0 = __int_as_float(e0.y), w1 = __int_as_float(e1.y);
                    float w2 = __int_as_float(e2.y), w3 = __int_as_float(e3.y);
                    ax += w0 * u0.x + w1 * u1.x + w2 * u2.x + w3 * u3.x;
                    ay += w0 * u0.y + w1 * u1.y + w2 * u2.y + w3 * u3.y;
                    az += w0 * u0.z + w1 * u1.z + w2 * u2.z + w3 * u3.z;
                    aw += w0 * u0.w + w1 * u1.w + w2 * u2.w + w3 * u3.w;
                }
                for (; i < e; i++) {
                    int2 e0 = __ldg(&g_edge[i]);
                    float w0 = __int_as_float(e0.y);
                    float4 u0 = xw4[e0.x * 8 + q];
                    ax += w0 * u0.x; ay += w0 * u0.y; az += w0 * u0.z; aw += w0 * u0.w;
                }
                ax = lrelu(ax); ay = lrelu(ay); az = lrelu(az); aw = lrelu(aw);
                ((float4*)g_y)[node * 8 + q] = make_float4(ax, ay, az, aw);
                ss0 += ax; ss1 += ay; ss2 += az; ss3 += aw;
                sq0 += ax * ax; sq1 += ay * ay; sq2 += az * az; sq3 += aw * aw;
            }
            __syncthreads();  // s_W (weights) free now — reuse as stats scratch
            s_W[t * 4 + 0] = ss0; s_W[t * 4 + 1] = ss1; s_W[t * 4 + 2] = ss2; s_W[t * 4 + 3] = ss3;
            s_W[4096 + t * 4 + 0] = sq0; s_W[4096 + t * 4 + 1] = sq1;
            s_W[4096 + t * 4 + 2] = sq2; s_W[4096 + t * 4 + 3] = sq3;
            __syncthreads();
            if (t < 32) {   // channel c = t; contributors tt with tt&7 == t>>2, component t&3
                int qq = t >> 2, comp = t & 3;
                float S = 0.f, Q = 0.f;
#pragma unroll
                for (int m = 0; m < 128; m++) {
                    int tt = qq + 8 * m;
                    S += s_W[tt * 4 + comp];
                    Q += s_W[4096 + tt * 4 + comp];
                }
                atomicAdd(&g_ssum[l * 32 + t], S);
                atomicAdd(&g_ssq [l * 32 + t], Q);
            }
        }
        gridbar();
    }

    // ---- FC0: warp-per-k-row streaming of fW0 (819 MB), BN fold inline ----
    {
        if (t < 32) {
            float sum = g_ssum[2 * 32 + t], sq = g_ssq[2 * 32 + t];
            float mean = sum / (float)NN;
            float var = sq / (float)NN - mean * mean;
            float a = gg2[t] * rsqrtf(var + EPSB);
            s_bnA[t] = a; s_bnB[t] = bt2[t] - mean * a;
        }
        __syncthreads();
        int start = b * KCH;
        int end = start + KCH; if (end > NN * 32) end = NN * 32;
        float a0 = 0.f, a1 = 0.f, a2 = 0.f, a3 = 0.f;
#pragma unroll 4
        for (int k = start + wid; k < end; k += 32) {
            float xk = g_y[k] * s_bnA[k & 31] + s_bnB[k & 31];
            float4 wv = *(const float4*)(fW0 + (size_t)k * 128 + 4 * lane);
            a0 += xk * wv.x; a1 += xk * wv.y; a2 += xk * wv.z; a3 += xk * wv.w;
        }
        __syncthreads();
        s_W[wid * 128 + 4 * lane + 0] = a0;
        s_W[wid * 128 + 4 * lane + 1] = a1;
        s_W[wid * 128 + 4 * lane + 2] = a2;
        s_W[wid * 128 + 4 * lane + 3] = a3;
        __syncthreads();
        if (t < 128) {
            float s = 0.f;
#pragma unroll
            for (int w32 = 0; w32 < 32; w32++) s += s_W[w32 * 128 + t];
            atomicAdd(&g_fc0[t], s);
        }
    }
    gridbar();  // final: g_fc0 complete

    // ---- FC tail (block 0) ----
    if (b == 0) {
        if (t < 128) s_W[t] = lrelu(g_fc0[t] + fb0[t]);
        __syncthreads();
        if (t < 64) {
            float a = fb1[t];
#pragma unroll 8
            for (int k = 0; k < 128; k++) a += s_W[k] * fW1[k * 64 + t];
            s_W[256 + t] = lrelu(a);
        }
        __syncthreads();
        if (t < 32) {
            float a = fb2[t];
#pragma unroll 8
            for (int k = 0; k < 64; k++) a += s_W[256 + k] * fW2[k * 32 + t];
            s_W[384 + t] = lrelu(a);
        }
        __syncthreads();
        if (t == 0) {
            float a = fb3[0];
#pragma unroll
            for (int k = 0; k < 32; k++) a += s_W[384 + k] * fW3[k];
            out[0] = a;
        }
    }
}

extern "C" void kernel_launch(void* const* d_in, const int* in_sizes, int n_in,
                              void* d_out, int out_size) {
    k_mega<<<NBLK, T>>>(
        d_in[0], (const float*)d_in[1],
        (const float*)d_in[2],  (const float*)d_in[3],  (const float*)d_in[4],  (const float*)d_in[5],
        (const float*)d_in[6],  (const float*)d_in[7],  (const float*)d_in[8],  (const float*)d_in[9],
        (const float*)d_in[10], (const float*)d_in[11], (const float*)d_in[12], (const float*)d_in[13],
        (const float*)d_in[14], (const float*)d_in[15], (const float*)d_in[16], (const float*)d_in[17],
        (const float*)d_in[18], (const float*)d_in[19], (const float*)d_in[20], (const float*)d_in[21],
        (float*)d_out);
    (void)in_sizes; (void)n_in; (void)out_size;
}

// round 6
// speedup vs baseline: 1.6853x; 1.2294x over previous
#include <cuda_runtime.h>

#define NN    50000
#define EE    1600000
#define EPSB  1e-5f
#define NBLK  148
#define TP    1024
#define CHUNK 338          // ceil(NN/NBLK)

// -------- static device scratch --------
__device__ int2  g_edge[EE];     // CSR: (src, weight bits)
__device__ int   g_deg[NN];
__device__ float g_dinv[NN];
__device__ int   g_ptr[NN + 1];
__device__ int   g_pos[NN];
__device__ int   g_part[NBLK];
__device__ float g_xw[NN * 32];
__device__ float g_y [NN * 32];
__device__ float g_ssum[3 * 32];
__device__ float g_ssq [3 * 32];
__device__ int   g_cnt[3];
__device__ float g_bnA[32];
__device__ float g_bnB[32];
__device__ float g_fc0[128];
__device__ unsigned g_cnt_bar = 0;
__device__ volatile unsigned g_gen = 0;

static __device__ __forceinline__ float lrelu(float v) {
    return v > 0.f ? v : 0.1f * v;
}

static __device__ __forceinline__ void gridbar() {
    __syncthreads();
    if (threadIdx.x == 0) {
        __threadfence();
        unsigned gen = g_gen;
        if (atomicAdd(&g_cnt_bar, 1u) == NBLK - 1) {
            g_cnt_bar = 0;
            __threadfence();
            g_gen = gen + 1;
        } else {
            while (g_gen == gen) __nanosleep(64);
        }
        __threadfence();
    }
    __syncthreads();
}

// ============ k_prep: init + histogram + scan + CSR place (persistent) ============
__global__ __launch_bounds__(TP, 1) void k_prep(const void* ei) {
    __shared__ int s_loc[CHUNK + 2];
    __shared__ int s_scan[256];
    __shared__ int s_wsum[32];
    __shared__ int s_is64;

    const int b = blockIdx.x, t = threadIdx.x;
    const int wid = t >> 5, lane = t & 31;

    if (t == 0) {
        const unsigned* w = (const unsigned*)ei;
        int nz = 0;
        for (int i = 0; i < 64; i++) nz += (w[2 * i + 1] != 0u);
        s_is64 = (nz == 0);
    }
    for (int i = b * TP + t; i < NN; i += NBLK * TP) g_deg[i] = 0;
    if (b == 0) {
        if (t < 96) { g_ssum[t] = 0.f; g_ssq[t] = 0.f; }
        if (t < 128) g_fc0[t] = 0.f;
        if (t < 3) g_cnt[t] = 0;
    }
    __syncthreads();
    const int is64 = s_is64;
    gridbar();

    // degree histogram (col only)
    if (is64) {
        const long long* p = (const long long*)ei;
        for (int e = b * TP + t; e < EE; e += NBLK * TP)
            atomicAdd(&g_deg[(int)p[EE + e]], 1);
    } else {
        const int* p = (const int*)ei;
        for (int e = b * TP + t; e < EE; e += NBLK * TP)
            atomicAdd(&g_deg[p[EE + e]], 1);
    }
    gridbar();

    // local scan + dinv
    {
        int base = b * CHUNK;
        int cnt = NN - base; if (cnt > CHUNK) cnt = CHUNK; if (cnt < 0) cnt = 0;
        int v = (t < cnt) ? g_deg[base + t] : 0;
        if (t < cnt) g_dinv[base + t] = rsqrtf((float)v + 2.f);
        int incl = v;
#pragma unroll
        for (int off = 1; off < 32; off <<= 1) {
            int u = __shfl_up_sync(0xffffffffu, incl, off);
            if (lane >= off) incl += u;
        }
        if (lane == 31) s_wsum[wid] = incl;
        __syncthreads();
        if (wid == 0) {
            int wv = s_wsum[lane];
            int winc = wv;
#pragma unroll
            for (int off = 1; off < 32; off <<= 1) {
                int u = __shfl_up_sync(0xffffffffu, winc, off);
                if (lane >= off) winc += u;
            }
            s_wsum[lane] = winc - wv;
            if (lane == 31) g_part[b] = winc;
        }
        __syncthreads();
        int excl = s_wsum[wid] + incl - v;
        if (t < cnt) s_loc[t] = excl;
    }
    gridbar();

    // block 0 scans partials
    if (b == 0) {
        int v = (t < NBLK) ? g_part[t] : 0;
        if (t < 256) s_scan[t] = v;
        __syncthreads();
#pragma unroll
        for (int off = 1; off < 256; off <<= 1) {
            int u = (t >= off && t < 256) ? s_scan[t - off] : 0;
            __syncthreads();
            if (t < 256) s_scan[t] += u;
            __syncthreads();
        }
        if (t < NBLK) g_part[t] = s_scan[t] - v;
        if (t == 0) g_ptr[NN] = EE;
    }
    gridbar();

    // emit ptr/pos
    {
        int base = b * CHUNK;
        int cnt = NN - base; if (cnt > CHUNK) cnt = CHUNK; if (cnt < 0) cnt = 0;
        int off = g_part[b];
        if (t < cnt) {
            int val = off + s_loc[t];
            g_ptr[base + t] = val;
            g_pos[base + t] = val;
        }
    }
    gridbar();

    // CSR placement
    if (is64) {
        const long long* p = (const long long*)ei;
        for (int e = b * TP + t; e < EE; e += NBLK * TP) {
            int r = (int)p[e], c = (int)p[EE + e];
            int slot = atomicAdd(&g_pos[c], 1);
            g_edge[slot] = make_int2(r, __float_as_int(g_dinv[r] * g_dinv[c]));
        }
    } else {
        const int* p = (const int*)ei;
        for (int e = b * TP + t; e < EE; e += NBLK * TP) {
            int r = p[e], c = p[EE + e];
            int slot = atomicAdd(&g_pos[c], 1);
            g_edge[slot] = make_int2(r, __float_as_int(g_dinv[r] * g_dinv[c]));
        }
    }
}

// ============ xw = (BN(x)) @ W : warp per node ============
template<int CIN, bool BN>
__global__ __launch_bounds__(256) void k_xw(const float* __restrict__ x,
                                            const float* __restrict__ W) {
    __shared__ float sW[CIN * 32];
    for (int i = threadIdx.x; i < CIN * 32; i += 256) sW[i] = W[i];
    __syncthreads();
    int warp = threadIdx.x >> 5, lane = threadIdx.x & 31;
    int node = blockIdx.x * 8 + warp;
    if (node >= NN) return;
    float acc = 0.f;
    if (CIN == 32) {
        float v = g_y[node * 32 + lane] * g_bnA[lane] + g_bnB[lane];
#pragma unroll
        for (int k = 0; k < 32; k++)
            acc += __shfl_sync(0xffffffffu, v, k) * sW[k * 32 + lane];
    } else {
        const float* xr = x + (size_t)node * 128;
        float v0 = xr[lane], v1 = xr[lane + 32], v2 = xr[lane + 64], v3 = xr[lane + 96];
#pragma unroll
        for (int k = 0; k < 32; k++) acc += __shfl_sync(0xffffffffu, v0, k) * sW[k * 32 + lane];
#pragma unroll
        for (int k = 0; k < 32; k++) acc += __shfl_sync(0xffffffffu, v1, k) * sW[(k + 32) * 32 + lane];
#pragma unroll
        for (int k = 0; k < 32; k++) acc += __shfl_sync(0xffffffffu, v2, k) * sW[(k + 64) * 32 + lane];
#pragma unroll
        for (int k = 0; k < 32; k++) acc += __shfl_sync(0xffffffffu, v3, k) * sW[(k + 96) * 32 + lane];
    }
    g_xw[node * 32 + lane] = acc;
}

// ============ gather + self loop + bias + lrelu + fused BN stats/fold ============
__global__ __launch_bounds__(256) void k_gather(int layer,
                                                const float* __restrict__ bb,
                                                const float* __restrict__ gg,
                                                const float* __restrict__ bt) {
    __shared__ float s_s[256 * 4], s_q[256 * 4];
    __shared__ bool last;
    int tid = blockIdx.x * 256 + threadIdx.x;
    int node = tid >> 3, q = threadIdx.x & 7;
    float ax = 0, ay = 0, az = 0, aw = 0;
    bool valid = (node < NN);
    if (valid) {
        const float4* xw4 = (const float4*)g_xw;
        float di = g_dinv[node];
        float sw = 2.f * di * di;
        float4 self = xw4[node * 8 + q];
        ax = self.x * sw + bb[q * 4 + 0];
        ay = self.y * sw + bb[q * 4 + 1];
        az = self.z * sw + bb[q * 4 + 2];
        aw = self.w * sw + bb[q * 4 + 3];
        int s = g_ptr[node], e = g_ptr[node + 1];
        int i = s;
        for (; i + 3 < e; i += 4) {
            int2 e0 = __ldg(&g_edge[i]),     e1 = __ldg(&g_edge[i + 1]);
            int2 e2 = __ldg(&g_edge[i + 2]), e3 = __ldg(&g_edge[i + 3]);
            float4 u0 = xw4[e0.x * 8 + q], u1 = xw4[e1.x * 8 + q];
            float4 u2 = xw4[e2.x * 8 + q], u3 = xw4[e3.x * 8 + q];
            float w0 = __int_as_float(e0.y), w1 = __int_as_float(e1.y);
            float w2 = __int_as_float(e2.y), w3 = __int_as_float(e3.y);
            ax += w0 * u0.x + w1 * u1.x + w2 * u2.x + w3 * u3.x;
            ay += w0 * u0.y + w1 * u1.y + w2 * u2.y + w3 * u3.y;
            az += w0 * u0.z + w1 * u1.z + w2 * u2.z + w3 * u3.z;
            aw += w0 * u0.w + w1 * u1.w + w2 * u2.w + w3 * u3.w;
        }
        for (; i < e; i++) {
            int2 e0 = __ldg(&g_edge[i]);
            float w0 = __int_as_float(e0.y);
            float4 u0 = xw4[e0.x * 8 + q];
            ax += w0 * u0.x; ay += w0 * u0.y; az += w0 * u0.z; aw += w0 * u0.w;
        }
        ax = lrelu(ax); ay = lrelu(ay); az = lrelu(az); aw = lrelu(aw);
        ((float4*)g_y)[node * 8 + q] = make_float4(ax, ay, az, aw);
    }
    // block-level stats reduce
    int t = threadIdx.x;
    s_s[t * 4 + 0] = valid ? ax : 0.f;  s_s[t * 4 + 1] = valid ? ay : 0.f;
    s_s[t * 4 + 2] = valid ? az : 0.f;  s_s[t * 4 + 3] = valid ? aw : 0.f;
    s_q[t * 4 + 0] = valid ? ax * ax : 0.f;  s_q[t * 4 + 1] = valid ? ay * ay : 0.f;
    s_q[t * 4 + 2] = valid ? az * az : 0.f;  s_q[t * 4 + 3] = valid ? aw * aw : 0.f;
    __syncthreads();
    if (t < 32) {  // channel c=t: contributors tt with tt&7==t>>2, component t&3
        int qq = t >> 2, comp = t & 3;
        float S = 0.f, Q = 0.f;
#pragma unroll
        for (int m = 0; m < 32; m++) {
            int tt = qq + 8 * m;
            S += s_s[tt * 4 + comp];
            Q += s_q[tt * 4 + comp];
        }
        atomicAdd(&g_ssum[layer * 32 + t], S);
        atomicAdd(&g_ssq [layer * 32 + t], Q);
    }
    __threadfence();
    __syncthreads();
    if (t == 0) {
        int v = atomicAdd(&g_cnt[layer], 1);
        last = (v == (int)gridDim.x - 1);
    }
    __syncthreads();
    if (last && t < 32) {
        float sum = atomicAdd(&g_ssum[layer * 32 + t], 0.f);
        float sq  = atomicAdd(&g_ssq [layer * 32 + t], 0.f);
        float mean = sum / (float)NN;
        float var  = sq / (float)NN - mean * mean;
        float a = gg[t] * rsqrtf(var + EPSB);
        g_bnA[t] = a;
        g_bnB[t] = bt[t] - mean * a;
    }
}

// ============ FC0: warp-per-k-row float4 streaming (2048 x 256) ============
#define FCROWS 782   // ceil(1.6M / 2048)
__global__ __launch_bounds__(256) void k_fc0(const float* __restrict__ W0) {
    __shared__ float s_acc[8 * 128];
    int wid = threadIdx.x >> 5, lane = threadIdx.x & 31;
    int k0 = blockIdx.x * FCROWS;
    int k1 = k0 + FCROWS; if (k1 > NN * 32) k1 = NN * 32;
    float a0 = 0.f, a1 = 0.f, a2 = 0.f, a3 = 0.f;
#pragma unroll 4
    for (int k = k0 + wid; k < k1; k += 8) {
        float xk = g_y[k] * g_bnA[k & 31] + g_bnB[k & 31];
        float4 wv = __ldg((const float4*)(W0 + (size_t)k * 128 + 4 * lane));
        a0 += xk * wv.x; a1 += xk * wv.y; a2 += xk * wv.z; a3 += xk * wv.w;
    }
    s_acc[wid * 128 + 4 * lane + 0] = a0;
    s_acc[wid * 128 + 4 * lane + 1] = a1;
    s_acc[wid * 128 + 4 * lane + 2] = a2;
    s_acc[wid * 128 + 4 * lane + 3] = a3;
    __syncthreads();
    int t = threadIdx.x;
    if (t < 128) {
        float s = 0.f;
#pragma unroll
        for (int w = 0; w < 8; w++) s += s_acc[w * 128 + t];
        atomicAdd(&g_fc0[t], s);
    }
}

// ============ FC tail ============
__global__ void k_fctail(const float* __restrict__ fb0,
                         const float* __restrict__ fW1, const float* __restrict__ fb1,
                         const float* __restrict__ fW2, const float* __restrict__ fb2,
                         const float* __restrict__ fW3, const float* __restrict__ fb3,
                         float* __restrict__ out) {
    __shared__ float h1[128], h2[64], h3[32];
    int t = threadIdx.x;
    h1[t] = lrelu(g_fc0[t] + fb0[t]);
    __syncthreads();
    if (t < 64) {
        float a = fb1[t];
#pragma unroll 8
        for (int k = 0; k < 128; k++) a += h1[k] * fW1[k * 64 + t];
        h2[t] = lrelu(a);
    }
    __syncthreads();
    if (t < 32) {
        float a = fb2[t];
#pragma unroll 8
        for (int k = 0; k < 64; k++) a += h2[k] * fW2[k * 32 + t];
        h3[t] = lrelu(a);
    }
    __syncthreads();
    if (t == 0) {
        float a = fb3[0];
#pragma unroll
        for (int k = 0; k < 32; k++) a += h3[k] * fW3[k];
        out[0] = a;
    }
}

extern "C" void kernel_launch(void* const* d_in, const int* in_sizes, int n_in,
                              void* d_out, int out_size) {
    const void*  ei  = d_in[0];
    const float* emb = (const float*)d_in[1];
    const float* cW[3] = {(const float*)d_in[2], (const float*)d_in[6], (const float*)d_in[10]};
    const float* cb[3] = {(const float*)d_in[3], (const float*)d_in[7], (const float*)d_in[11]};
    const float* gg[3] = {(const float*)d_in[4], (const float*)d_in[8], (const float*)d_in[12]};
    const float* bt[3] = {(const float*)d_in[5], (const float*)d_in[9], (const float*)d_in[13]};
    const float* fW0 = (const float*)d_in[14];
    const float* fb0 = (const float*)d_in[15];
    float* out = (float*)d_out;

    k_prep<<<NBLK, TP>>>(ei);

    k_xw<128, false><<<(NN + 7) / 8, 256>>>(emb, cW[0]);
    k_gather<<<(NN * 8 + 255) / 256, 256>>>(0, cb[0], gg[0], bt[0]);

    k_xw<32, true><<<(NN + 7) / 8, 256>>>(nullptr, cW[1]);
    k_gather<<<(NN * 8 + 255) / 256, 256>>>(1, cb[1], gg[1], bt[1]);

    k_xw<32, true><<<(NN + 7) / 8, 256>>>(nullptr, cW[2]);
    k_gather<<<(NN * 8 + 255) / 256, 256>>>(2, cb[2], gg[2], bt[2]);

    k_fc0<<<2048, 256>>>(fW0);
    k_fctail<<<1, 128>>>(fb0,
                         (const float*)d_in[16], (const float*)d_in[17],
                         (const float*)d_in[18], (const float*)d_in[19],
                         (const float*)d_in[20], (const float*)d_in[21],
                         out);
    (void)in_sizes; (void)n_in; (void)out_size;
}

// round 7
// speedup vs baseline: 1.7955x; 1.0654x over previous
#include <cuda_runtime.h>

#define NN    50000
#define EE    1600000
#define EPSB  1e-5f
#define NBLK  148
#define TP    1024
#define CHUNK 338          // ceil(NN/NBLK)

// -------- static device scratch --------
__device__ int2  g_edge[EE];     // CSR: (src, weight bits)
__device__ int   g_deg[NN];
__device__ float g_dinv[NN];
__device__ int   g_ptr[NN + 1];
__device__ int   g_pos[NN];
__device__ int   g_part[NBLK];
__device__ float g_xw[NN * 32];
__device__ float g_y [NN * 32];
__device__ float g_ssum[3 * 32];
__device__ float g_ssq [3 * 32];
__device__ int   g_cnt[3];
__device__ int   g_cntf;
__device__ float g_bnA[32];
__device__ float g_bnB[32];
__device__ float g_fc0[128];
__device__ unsigned g_cnt_bar = 0;
__device__ volatile unsigned g_gen = 0;

static __device__ __forceinline__ float lrelu(float v) {
    return v > 0.f ? v : 0.1f * v;
}

static __device__ __forceinline__ void gridbar() {
    __syncthreads();
    if (threadIdx.x == 0) {
        __threadfence();
        unsigned gen = g_gen;
        if (atomicAdd(&g_cnt_bar, 1u) == NBLK - 1) {
            g_cnt_bar = 0;
            __threadfence();
            g_gen = gen + 1;
        } else {
            while (g_gen == gen) __nanosleep(64);
        }
        __threadfence();
    }
    __syncthreads();
}

// ============ k_prep: init + histogram + scan + CSR place (persistent) ============
__global__ __launch_bounds__(TP, 1) void k_prep(const void* ei) {
    __shared__ int s_loc[CHUNK + 2];
    __shared__ int s_scan[256];
    __shared__ int s_wsum[32];
    __shared__ int s_is64;

    const int b = blockIdx.x, t = threadIdx.x;
    const int wid = t >> 5, lane = t & 31;

    if (t == 0) {
        const unsigned* w = (const unsigned*)ei;
        int nz = 0;
        for (int i = 0; i < 64; i++) nz += (w[2 * i + 1] != 0u);
        s_is64 = (nz == 0);
    }
    for (int i = b * TP + t; i < NN; i += NBLK * TP) g_deg[i] = 0;
    if (b == 0) {
        if (t < 96) { g_ssum[t] = 0.f; g_ssq[t] = 0.f; }
        if (t < 128) g_fc0[t] = 0.f;
        if (t < 3) g_cnt[t] = 0;
        if (t == 0) g_cntf = 0;
    }
    __syncthreads();
    const int is64 = s_is64;
    gridbar();

    if (is64) {
        const long long* p = (const long long*)ei;
        for (int e = b * TP + t; e < EE; e += NBLK * TP)
            atomicAdd(&g_deg[(int)p[EE + e]], 1);
    } else {
        const int* p = (const int*)ei;
        for (int e = b * TP + t; e < EE; e += NBLK * TP)
            atomicAdd(&g_deg[p[EE + e]], 1);
    }
    gridbar();

    {
        int base = b * CHUNK;
        int cnt = NN - base; if (cnt > CHUNK) cnt = CHUNK; if (cnt < 0) cnt = 0;
        int v = (t < cnt) ? g_deg[base + t] : 0;
        if (t < cnt) g_dinv[base + t] = rsqrtf((float)v + 2.f);
        int incl = v;
#pragma unroll
        for (int off = 1; off < 32; off <<= 1) {
            int u = __shfl_up_sync(0xffffffffu, incl, off);
            if (lane >= off) incl += u;
        }
        if (lane == 31) s_wsum[wid] = incl;
        __syncthreads();
        if (wid == 0) {
            int wv = s_wsum[lane];
            int winc = wv;
#pragma unroll
            for (int off = 1; off < 32; off <<= 1) {
                int u = __shfl_up_sync(0xffffffffu, winc, off);
                if (lane >= off) winc += u;
            }
            s_wsum[lane] = winc - wv;
            if (lane == 31) g_part[b] = winc;
        }
        __syncthreads();
        int excl = s_wsum[wid] + incl - v;
        if (t < cnt) s_loc[t] = excl;
    }
    gridbar();

    if (b == 0) {
        int v = (t < NBLK) ? g_part[t] : 0;
        if (t < 256) s_scan[t] = v;
        __syncthreads();
#pragma unroll
        for (int off = 1; off < 256; off <<= 1) {
            int u = (t >= off && t < 256) ? s_scan[t - off] : 0;
            __syncthreads();
            if (t < 256) s_scan[t] += u;
            __syncthreads();
        }
        if (t < NBLK) g_part[t] = s_scan[t] - v;
        if (t == 0) g_ptr[NN] = EE;
    }
    gridbar();

    {
        int base = b * CHUNK;
        int cnt = NN - base; if (cnt > CHUNK) cnt = CHUNK; if (cnt < 0) cnt = 0;
        int off = g_part[b];
        if (t < cnt) {
            int val = off + s_loc[t];
            g_ptr[base + t] = val;
            g_pos[base + t] = val;
        }
    }
    gridbar();

    if (is64) {
        const long long* p = (const long long*)ei;
        for (int e = b * TP + t; e < EE; e += NBLK * TP) {
            int r = (int)p[e], c = (int)p[EE + e];
            int slot = atomicAdd(&g_pos[c], 1);
            g_edge[slot] = make_int2(r, __float_as_int(g_dinv[r] * g_dinv[c]));
        }
    } else {
        const int* p = (const int*)ei;
        for (int e = b * TP + t; e < EE; e += NBLK * TP) {
            int r = p[e], c = p[EE + e];
            int slot = atomicAdd(&g_pos[c], 1);
            g_edge[slot] = make_int2(r, __float_as_int(g_dinv[r] * g_dinv[c]));
        }
    }
}

// ============ xw = (BN(x)) @ W : thread per node, register accumulators ============
template<int CIN, bool BN>
__global__ __launch_bounds__(256) void k_xw(const float* __restrict__ x,
                                            const float* __restrict__ W) {
    __shared__ float4 sW4[CIN * 8];     // W[k][j] grouped as float4 over j
    __shared__ float  sA[CIN > 32 ? 1 : 32], sB[CIN > 32 ? 1 : 32];
    for (int i = threadIdx.x; i < CIN * 8; i += 256)
        sW4[i] = ((const float4*)W)[i];
    if (BN && threadIdx.x < 32) {
        sA[threadIdx.x] = g_bnA[threadIdx.x];
        sB[threadIdx.x] = g_bnB[threadIdx.x];
    }
    __syncthreads();
    int node = blockIdx.x * 256 + threadIdx.x;
    if (node >= NN) return;
    const float4* xr4 = BN ? ((const float4*)g_y + node * 8)
                           : ((const float4*)(x + (size_t)node * CIN));
    float4 acc[8];
#pragma unroll
    for (int j = 0; j < 8; j++) acc[j] = make_float4(0.f, 0.f, 0.f, 0.f);

#define XW_STEP(xs, kidx)                                         \
    {                                                             \
        float _xs = (xs);                                         \
        _Pragma("unroll")                                         \
        for (int j = 0; j < 8; j++) {                             \
            float4 w = sW4[(kidx) * 8 + j];                       \
            acc[j].x += _xs * w.x; acc[j].y += _xs * w.y;         \
            acc[j].z += _xs * w.z; acc[j].w += _xs * w.w;         \
        }                                                         \
    }

#pragma unroll
    for (int k4 = 0; k4 < CIN / 4; k4++) {
        float4 xv = xr4[k4];
        if (BN) {
            xv.x = xv.x * sA[4 * k4 + 0] + sB[4 * k4 + 0];
            xv.y = xv.y * sA[4 * k4 + 1] + sB[4 * k4 + 1];
            xv.z = xv.z * sA[4 * k4 + 2] + sB[4 * k4 + 2];
            xv.w = xv.w * sA[4 * k4 + 3] + sB[4 * k4 + 3];
        }
        XW_STEP(xv.x, 4 * k4 + 0);
        XW_STEP(xv.y, 4 * k4 + 1);
        XW_STEP(xv.z, 4 * k4 + 2);
        XW_STEP(xv.w, 4 * k4 + 3);
    }
#undef XW_STEP
    float4* o4 = (float4*)g_xw + node * 8;
#pragma unroll
    for (int j = 0; j < 8; j++) o4[j] = acc[j];
}

// ============ gather + self loop + bias + lrelu + fused BN stats/fold ============
__global__ __launch_bounds__(256) void k_gather(int layer,
                                                const float* __restrict__ bb,
                                                const float* __restrict__ gg,
                                                const float* __restrict__ bt) {
    __shared__ float s_s[256 * 4], s_q[256 * 4];
    __shared__ bool last;
    int tid = blockIdx.x * 256 + threadIdx.x;
    int node = tid >> 3, q = threadIdx.x & 7;
    float ax = 0, ay = 0, az = 0, aw = 0;
    bool valid = (node < NN);
    if (valid) {
        const float4* xw4 = (const float4*)g_xw;
        float di = g_dinv[node];
        float sw = 2.f * di * di;
        float4 self = xw4[node * 8 + q];
        ax = self.x * sw + bb[q * 4 + 0];
        ay = self.y * sw + bb[q * 4 + 1];
        az = self.z * sw + bb[q * 4 + 2];
        aw = self.w * sw + bb[q * 4 + 3];
        int s = g_ptr[node], e = g_ptr[node + 1];
        int i = s;
        for (; i + 3 < e; i += 4) {
            int2 e0 = __ldg(&g_edge[i]),     e1 = __ldg(&g_edge[i + 1]);
            int2 e2 = __ldg(&g_edge[i + 2]), e3 = __ldg(&g_edge[i + 3]);
            float4 u0 = xw4[e0.x * 8 + q], u1 = xw4[e1.x * 8 + q];
            float4 u2 = xw4[e2.x * 8 + q], u3 = xw4[e3.x * 8 + q];
            float w0 = __int_as_float(e0.y), w1 = __int_as_float(e1.y);
            float w2 = __int_as_float(e2.y), w3 = __int_as_float(e3.y);
            ax += w0 * u0.x + w1 * u1.x + w2 * u2.x + w3 * u3.x;
            ay += w0 * u0.y + w1 * u1.y + w2 * u2.y + w3 * u3.y;
            az += w0 * u0.z + w1 * u1.z + w2 * u2.z + w3 * u3.z;
            aw += w0 * u0.w + w1 * u1.w + w2 * u2.w + w3 * u3.w;
        }
        for (; i < e; i++) {
            int2 e0 = __ldg(&g_edge[i]);
            float w0 = __int_as_float(e0.y);
            float4 u0 = xw4[e0.x * 8 + q];
            ax += w0 * u0.x; ay += w0 * u0.y; az += w0 * u0.z; aw += w0 * u0.w;
        }
        ax = lrelu(ax); ay = lrelu(ay); az = lrelu(az); aw = lrelu(aw);
        ((float4*)g_y)[node * 8 + q] = make_float4(ax, ay, az, aw);
    }
    int t = threadIdx.x;
    s_s[t * 4 + 0] = valid ? ax : 0.f;  s_s[t * 4 + 1] = valid ? ay : 0.f;
    s_s[t * 4 + 2] = valid ? az : 0.f;  s_s[t * 4 + 3] = valid ? aw : 0.f;
    s_q[t * 4 + 0] = valid ? ax * ax : 0.f;  s_q[t * 4 + 1] = valid ? ay * ay : 0.f;
    s_q[t * 4 + 2] = valid ? az * az : 0.f;  s_q[t * 4 + 3] = valid ? aw * aw : 0.f;
    __syncthreads();
    if (t < 32) {
        int qq = t >> 2, comp = t & 3;
        float S = 0.f, Q = 0.f;
#pragma unroll
        for (int m = 0; m < 32; m++) {
            int tt = qq + 8 * m;
            S += s_s[tt * 4 + comp];
            Q += s_q[tt * 4 + comp];
        }
        atomicAdd(&g_ssum[layer * 32 + t], S);
        atomicAdd(&g_ssq [layer * 32 + t], Q);
    }
    __threadfence();
    __syncthreads();
    if (t == 0) {
        int v = atomicAdd(&g_cnt[layer], 1);
        last = (v == (int)gridDim.x - 1);
    }
    __syncthreads();
    if (last && t < 32) {
        float sum = atomicAdd(&g_ssum[layer * 32 + t], 0.f);
        float sq  = atomicAdd(&g_ssq [layer * 32 + t], 0.f);
        float mean = sum / (float)NN;
        float var  = sq / (float)NN - mean * mean;
        float a = gg[t] * rsqrtf(var + EPSB);
        g_bnA[t] = a;
        g_bnB[t] = bt[t] - mean * a;
    }
}

// ============ FC0 + fused FC tail in last block ============
#define FCROWS 782   // ceil(1.6M / 2048)
__global__ __launch_bounds__(256) void k_fc0(const float* __restrict__ W0,
                                             const float* __restrict__ fb0,
                                             const float* __restrict__ fW1, const float* __restrict__ fb1,
                                             const float* __restrict__ fW2, const float* __restrict__ fb2,
                                             const float* __restrict__ fW3, const float* __restrict__ fb3,
                                             float* __restrict__ out) {
    __shared__ float s_acc[8 * 128];
    __shared__ bool last;
    int wid = threadIdx.x >> 5, lane = threadIdx.x & 31;
    int k0 = blockIdx.x * FCROWS;
    int k1 = k0 + FCROWS; if (k1 > NN * 32) k1 = NN * 32;
    float a0 = 0.f, a1 = 0.f, a2 = 0.f, a3 = 0.f;
#pragma unroll 4
    for (int k = k0 + wid; k < k1; k += 8) {
        float xk = g_y[k] * g_bnA[k & 31] + g_bnB[k & 31];
        float4 wv = __ldg((const float4*)(W0 + (size_t)k * 128 + 4 * lane));
        a0 += xk * wv.x; a1 += xk * wv.y; a2 += xk * wv.z; a3 += xk * wv.w;
    }
    s_acc[wid * 128 + 4 * lane + 0] = a0;
    s_acc[wid * 128 + 4 * lane + 1] = a1;
    s_acc[wid * 128 + 4 * lane + 2] = a2;
    s_acc[wid * 128 + 4 * lane + 3] = a3;
    __syncthreads();
    int t = threadIdx.x;
    if (t < 128) {
        float s = 0.f;
#pragma unroll
        for (int w = 0; w < 8; w++) s += s_acc[w * 128 + t];
        atomicAdd(&g_fc0[t], s);
    }
    __threadfence();
    __syncthreads();
    if (t == 0) {
        int v = atomicAdd(&g_cntf, 1);
        last = (v == (int)gridDim.x - 1);
    }
    __syncthreads();
    if (last) {
        // FC tail: 128 -> 64 -> 32 -> 1 (reuse s_acc as h buffers)
        if (t < 128) s_acc[t] = lrelu(atomicAdd(&g_fc0[t], 0.f) + fb0[t]);
        __syncthreads();
        if (t < 64) {
            float a = fb1[t];
#pragma unroll 8
            for (int k = 0; k < 128; k++) a += s_acc[k] * fW1[k * 64 + t];
            s_acc[256 + t] = lrelu(a);
        }
        __syncthreads();
        if (t < 32) {
            float a = fb2[t];
#pragma unroll 8
            for (int k = 0; k < 64; k++) a += s_acc[256 + k] * fW2[k * 32 + t];
            s_acc[384 + t] = lrelu(a);
        }
        __syncthreads();
        if (t == 0) {
            float a = fb3[0];
#pragma unroll
            for (int k = 0; k < 32; k++) a += s_acc[384 + k] * fW3[k];
            out[0] = a;
        }
    }
}

extern "C" void kernel_launch(void* const* d_in, const int* in_sizes, int n_in,
                              void* d_out, int out_size) {
    const void*  ei  = d_in[0];
    const float* emb = (const float*)d_in[1];
    const float* cW[3] = {(const float*)d_in[2], (const float*)d_in[6], (const float*)d_in[10]};
    const float* cb[3] = {(const float*)d_in[3], (const float*)d_in[7], (const float*)d_in[11]};
    const float* gg[3] = {(const float*)d_in[4], (const float*)d_in[8], (const float*)d_in[12]};
    const float* bt[3] = {(const float*)d_in[5], (const float*)d_in[9], (const float*)d_in[13]};
    float* out = (float*)d_out;

    k_prep<<<NBLK, TP>>>(ei);

    k_xw<128, false><<<(NN + 255) / 256, 256>>>(emb, cW[0]);
    k_gather<<<(NN * 8 + 255) / 256, 256>>>(0, cb[0], gg[0], bt[0]);

    k_xw<32, true><<<(NN + 255) / 256, 256>>>(nullptr, cW[1]);
    k_gather<<<(NN * 8 + 255) / 256, 256>>>(1, cb[1], gg[1], bt[1]);

    k_xw<32, true><<<(NN + 255) / 256, 256>>>(nullptr, cW[2]);
    k_gather<<<(NN * 8 + 255) / 256, 256>>>(2, cb[2], gg[2], bt[2]);

    k_fc0<<<2048, 256>>>((const float*)d_in[14], (const float*)d_in[15],
                         (const float*)d_in[16], (const float*)d_in[17],
                         (const float*)d_in[18], (const float*)d_in[19],
                         (const float*)d_in[20], (const float*)d_in[21],
                         out);
    (void)in_sizes; (void)n_in; (void)out_size;
}

// round 8
// speedup vs baseline: 1.8218x; 1.0147x over previous
#include <cuda_runtime.h>

#define NN    50000
#define EE    1600000
#define EPSB  1e-5f
#define NBLK  148
#define TP    1024
#define CHUNK 338          // ceil(NN/NBLK)

// -------- constant-memory weights (copied in kernel_launch, D2D async) --------
__constant__ unsigned long long c_W0[2048];   // 128*32 floats as f32x2 pairs
__constant__ unsigned long long c_W1[512];    // 32*32
__constant__ unsigned long long c_W2[512];    // 32*32

// -------- static device scratch --------
__device__ __align__(16) int2 g_edge[EE];   // CSR: (src, weight bits)
__device__ int   g_deg[NN];
__device__ float g_dinv[NN];
__device__ int   g_ptr[NN + 1];
__device__ int   g_pos[NN];
__device__ int   g_part[NBLK];
__device__ float g_xw[NN * 32];
__device__ float g_y [NN * 32];
__device__ float g_ssum[3 * 32];
__device__ float g_ssq [3 * 32];
__device__ int   g_cnt[3];
__device__ int   g_cntf;
__device__ float g_bnA[32];
__device__ float g_bnB[32];
__device__ float g_fc0[128];
__device__ unsigned g_cnt_bar = 0;
__device__ volatile unsigned g_gen = 0;

static __device__ __forceinline__ float lrelu(float v) {
    return v > 0.f ? v : 0.1f * v;
}

#define FMA2(acc, xx, ww) \
    asm("fma.rn.f32x2 %0, %1, %2, %0;" : "+l"(acc) : "l"(xx), "l"(ww))

static __device__ __forceinline__ unsigned long long packdup(float x) {
    unsigned long long r;
    unsigned xi = __float_as_uint(x);
    asm("mov.b64 %0, {%1, %1};" : "=l"(r) : "r"(xi));
    return r;
}
static __device__ __forceinline__ float2 unpack2(unsigned long long v) {
    unsigned lo, hi;
    asm("mov.b64 {%0, %1}, %2;" : "=r"(lo), "=r"(hi) : "l"(v));
    return make_float2(__uint_as_float(lo), __uint_as_float(hi));
}

static __device__ __forceinline__ void gridbar() {
    __syncthreads();
    if (threadIdx.x == 0) {
        __threadfence();
        unsigned gen = g_gen;
        if (atomicAdd(&g_cnt_bar, 1u) == NBLK - 1) {
            g_cnt_bar = 0;
            __threadfence();
            g_gen = gen + 1;
        } else {
            while (g_gen == gen) __nanosleep(64);
        }
        __threadfence();
    }
    __syncthreads();
}

// ============ k_prep: init + histogram + scan + CSR place (persistent) ============
__global__ __launch_bounds__(TP, 1) void k_prep(const void* ei) {
    __shared__ int s_loc[CHUNK + 2];
    __shared__ int s_scan[256];
    __shared__ int s_wsum[32];
    __shared__ int s_is64;

    const int b = blockIdx.x, t = threadIdx.x;
    const int wid = t >> 5, lane = t & 31;

    if (t == 0) {
        const unsigned* w = (const unsigned*)ei;
        int nz = 0;
        for (int i = 0; i < 64; i++) nz += (w[2 * i + 1] != 0u);
        s_is64 = (nz == 0);
    }
    for (int i = b * TP + t; i < NN; i += NBLK * TP) g_deg[i] = 0;
    if (b == 0) {
        if (t < 96) { g_ssum[t] = 0.f; g_ssq[t] = 0.f; }
        if (t < 128) g_fc0[t] = 0.f;
        if (t < 3) g_cnt[t] = 0;
        if (t == 0) g_cntf = 0;
    }
    __syncthreads();
    const int is64 = s_is64;
    gridbar();

    if (is64) {
        const long long* p = (const long long*)ei;
        for (int e = b * TP + t; e < EE; e += NBLK * TP)
            atomicAdd(&g_deg[(int)p[EE + e]], 1);
    } else {
        const int* p = (const int*)ei;
        for (int e = b * TP + t; e < EE; e += NBLK * TP)
            atomicAdd(&g_deg[p[EE + e]], 1);
    }
    gridbar();

    {
        int base = b * CHUNK;
        int cnt = NN - base; if (cnt > CHUNK) cnt = CHUNK; if (cnt < 0) cnt = 0;
        int v = (t < cnt) ? g_deg[base + t] : 0;
        if (t < cnt) g_dinv[base + t] = rsqrtf((float)v + 2.f);
        int incl = v;
#pragma unroll
        for (int off = 1; off < 32; off <<= 1) {
            int u = __shfl_up_sync(0xffffffffu, incl, off);
            if (lane >= off) incl += u;
        }
        if (lane == 31) s_wsum[wid] = incl;
        __syncthreads();
        if (wid == 0) {
            int wv = s_wsum[lane];
            int winc = wv;
#pragma unroll
            for (int off = 1; off < 32; off <<= 1) {
                int u = __shfl_up_sync(0xffffffffu, winc, off);
                if (lane >= off) winc += u;
            }
            s_wsum[lane] = winc - wv;
            if (lane == 31) g_part[b] = winc;
        }
        __syncthreads();
        int excl = s_wsum[wid] + incl - v;
        if (t < cnt) s_loc[t] = excl;
    }
    gridbar();

    if (b == 0) {
        int v = (t < NBLK) ? g_part[t] : 0;
        if (t < 256) s_scan[t] = v;
        __syncthreads();
#pragma unroll
        for (int off = 1; off < 256; off <<= 1) {
            int u = (t >= off && t < 256) ? s_scan[t - off] : 0;
            __syncthreads();
            if (t < 256) s_scan[t] += u;
            __syncthreads();
        }
        if (t < NBLK) g_part[t] = s_scan[t] - v;
        if (t == 0) g_ptr[NN] = EE;
    }
    gridbar();

    {
        int base = b * CHUNK;
        int cnt = NN - base; if (cnt > CHUNK) cnt = CHUNK; if (cnt < 0) cnt = 0;
        int off = g_part[b];
        if (t < cnt) {
            int val = off + s_loc[t];
            g_ptr[base + t] = val;
            g_pos[base + t] = val;
        }
    }
    gridbar();

    if (is64) {
        const long long* p = (const long long*)ei;
        for (int e = b * TP + t; e < EE; e += NBLK * TP) {
            int r = (int)p[e], c = (int)p[EE + e];
            int slot = atomicAdd(&g_pos[c], 1);
            g_edge[slot] = make_int2(r, __float_as_int(g_dinv[r] * g_dinv[c]));
        }
    } else {
        const int* p = (const int*)ei;
        for (int e = b * TP + t; e < EE; e += NBLK * TP) {
            int r = p[e], c = p[EE + e];
            int slot = atomicAdd(&g_pos[c], 1);
            g_edge[slot] = make_int2(r, __float_as_int(g_dinv[r] * g_dinv[c]));
        }
    }
}

// ============ xw128 = emb @ W0 : thread/node, constants + f32x2 ============
__global__ __launch_bounds__(256) void k_xw128(const float* __restrict__ x) {
    int node = blockIdx.x * 256 + threadIdx.x;
    if (node >= NN) return;
    const float4* xr4 = (const float4*)(x + (size_t)node * 128);
    unsigned long long acc[16];
#pragma unroll
    for (int j = 0; j < 16; j++) acc[j] = 0ull;
#pragma unroll 4
    for (int k4 = 0; k4 < 32; k4++) {
        float4 xv = xr4[k4];
        unsigned long long x0 = packdup(xv.x), x1 = packdup(xv.y);
        unsigned long long x2 = packdup(xv.z), x3 = packdup(xv.w);
#pragma unroll
        for (int j = 0; j < 16; j++) {
            FMA2(acc[j], x0, c_W0[(4 * k4 + 0) * 16 + j]);
            FMA2(acc[j], x1, c_W0[(4 * k4 + 1) * 16 + j]);
            FMA2(acc[j], x2, c_W0[(4 * k4 + 2) * 16 + j]);
            FMA2(acc[j], x3, c_W0[(4 * k4 + 3) * 16 + j]);
        }
    }
    float4* o4 = (float4*)g_xw + node * 8;
#pragma unroll
    for (int j = 0; j < 8; j++) {
        float2 a = unpack2(acc[2 * j]), bq = unpack2(acc[2 * j + 1]);
        o4[j] = make_float4(a.x, a.y, bq.x, bq.y);
    }
}

// ============ xw32 = BN(y) @ W : thread/node, constants + f32x2 ============
template<int LAYER>
__global__ __launch_bounds__(256) void k_xw32() {
    __shared__ float sA[32], sB[32];
    if (threadIdx.x < 32) {
        sA[threadIdx.x] = g_bnA[threadIdx.x];
        sB[threadIdx.x] = g_bnB[threadIdx.x];
    }
    __syncthreads();
    int node = blockIdx.x * 256 + threadIdx.x;
    if (node >= NN) return;
    const float4* xr4 = (const float4*)g_y + node * 8;
    unsigned long long acc[16];
#pragma unroll
    for (int j = 0; j < 16; j++) acc[j] = 0ull;
#pragma unroll
    for (int k4 = 0; k4 < 8; k4++) {
        float4 xv = xr4[k4];
        xv.x = xv.x * sA[4 * k4 + 0] + sB[4 * k4 + 0];
        xv.y = xv.y * sA[4 * k4 + 1] + sB[4 * k4 + 1];
        xv.z = xv.z * sA[4 * k4 + 2] + sB[4 * k4 + 2];
        xv.w = xv.w * sA[4 * k4 + 3] + sB[4 * k4 + 3];
        unsigned long long x0 = packdup(xv.x), x1 = packdup(xv.y);
        unsigned long long x2 = packdup(xv.z), x3 = packdup(xv.w);
        const unsigned long long* W = (LAYER == 1) ? c_W1 : c_W2;
#pragma unroll
        for (int j = 0; j < 16; j++) {
            FMA2(acc[j], x0, W[(4 * k4 + 0) * 16 + j]);
            FMA2(acc[j], x1, W[(4 * k4 + 1) * 16 + j]);
            FMA2(acc[j], x2, W[(4 * k4 + 2) * 16 + j]);
            FMA2(acc[j], x3, W[(4 * k4 + 3) * 16 + j]);
        }
    }
    float4* o4 = (float4*)g_xw + node * 8;
#pragma unroll
    for (int j = 0; j < 8; j++) {
        float2 a = unpack2(acc[2 * j]), bq = unpack2(acc[2 * j + 1]);
        o4[j] = make_float4(a.x, a.y, bq.x, bq.y);
    }
}

// ============ gather + self loop + bias + lrelu + fused BN stats/fold ============
__global__ __launch_bounds__(256) void k_gather(int layer,
                                                const float* __restrict__ bb,
                                                const float* __restrict__ gg,
                                                const float* __restrict__ bt) {
    __shared__ float s_s[256 * 4], s_q[256 * 4];
    __shared__ bool last;
    int tid = blockIdx.x * 256 + threadIdx.x;
    int node = tid >> 3, q = threadIdx.x & 7;
    float ax = 0, ay = 0, az = 0, aw = 0;
    bool valid = (node < NN);
    if (valid) {
        const float4* xw4 = (const float4*)g_xw;
        float di = g_dinv[node];
        float sw = 2.f * di * di;
        float4 self = xw4[node * 8 + q];
        ax = self.x * sw + bb[q * 4 + 0];
        ay = self.y * sw + bb[q * 4 + 1];
        az = self.z * sw + bb[q * 4 + 2];
        aw = self.w * sw + bb[q * 4 + 3];
        int s = g_ptr[node], e = g_ptr[node + 1];
        int i = s;
        // peel to even index for int4 (2-edge) loads
        if ((i & 1) && i < e) {
            int2 e0 = __ldg(&g_edge[i]);
            float w0 = __int_as_float(e0.y);
            float4 u0 = xw4[e0.x * 8 + q];
            ax += w0 * u0.x; ay += w0 * u0.y; az += w0 * u0.z; aw += w0 * u0.w;
            i++;
        }
        const int4* ep = (const int4*)g_edge;
        for (; i + 7 < e; i += 8) {
            int4 p0 = __ldg(ep + (i >> 1) + 0);
            int4 p1 = __ldg(ep + (i >> 1) + 1);
            int4 p2 = __ldg(ep + (i >> 1) + 2);
            int4 p3 = __ldg(ep + (i >> 1) + 3);
            float4 u0 = xw4[p0.x * 8 + q], u1 = xw4[p0.z * 8 + q];
            float4 u2 = xw4[p1.x * 8 + q], u3 = xw4[p1.z * 8 + q];
            float4 u4 = xw4[p2.x * 8 + q], u5 = xw4[p2.z * 8 + q];
            float4 u6 = xw4[p3.x * 8 + q], u7 = xw4[p3.z * 8 + q];
            float w0 = __int_as_float(p0.y), w1 = __int_as_float(p0.w);
            float w2 = __int_as_float(p1.y), w3 = __int_as_float(p1.w);
            float w4 = __int_as_float(p2.y), w5 = __int_as_float(p2.w);
            float w6 = __int_as_float(p3.y), w7 = __int_as_float(p3.w);
            ax += w0 * u0.x + w1 * u1.x + w2 * u2.x + w3 * u3.x
                + w4 * u4.x + w5 * u5.x + w6 * u6.x + w7 * u7.x;
            ay += w0 * u0.y + w1 * u1.y + w2 * u2.y + w3 * u3.y
                + w4 * u4.y + w5 * u5.y + w6 * u6.y + w7 * u7.y;
            az += w0 * u0.z + w1 * u1.z + w2 * u2.z + w3 * u3.z
                + w4 * u4.z + w5 * u5.z + w6 * u6.z + w7 * u7.z;
            aw += w0 * u0.w + w1 * u1.w + w2 * u2.w + w3 * u3.w
                + w4 * u4.w + w5 * u5.w + w6 * u6.w + w7 * u7.w;
        }
        for (; i + 1 < e; i += 2) {
            int4 p0 = __ldg(ep + (i >> 1));
            float4 u0 = xw4[p0.x * 8 + q], u1 = xw4[p0.z * 8 + q];
            float w0 = __int_as_float(p0.y), w1 = __int_as_float(p0.w);
            ax += w0 * u0.x + w1 * u1.x;
            ay += w0 * u0.y + w1 * u1.y;
            az += w0 * u0.z + w1 * u1.z;
            aw += w0 * u0.w + w1 * u1.w;
        }
        if (i < e) {
            int2 e0 = __ldg(&g_edge[i]);
            float w0 = __int_as_float(e0.y);
            float4 u0 = xw4[e0.x * 8 + q];
            ax += w0 * u0.x; ay += w0 * u0.y; az += w0 * u0.z; aw += w0 * u0.w;
        }
        ax = lrelu(ax); ay = lrelu(ay); az = lrelu(az); aw = lrelu(aw);
        ((float4*)g_y)[node * 8 + q] = make_float4(ax, ay, az, aw);
    }
    int t = threadIdx.x;
    s_s[t * 4 + 0] = valid ? ax : 0.f;  s_s[t * 4 + 1] = valid ? ay : 0.f;
    s_s[t * 4 + 2] = valid ? az : 0.f;  s_s[t * 4 + 3] = valid ? aw : 0.f;
    s_q[t * 4 + 0] = valid ? ax * ax : 0.f;  s_q[t * 4 + 1] = valid ? ay * ay : 0.f;
    s_q[t * 4 + 2] = valid ? az * az : 0.f;  s_q[t * 4 + 3] = valid ? aw * aw : 0.f;
    __syncthreads();
    if (t < 32) {
        int qq = t >> 2, comp = t & 3;
        float S = 0.f, Q = 0.f;
#pragma unroll
        for (int m = 0; m < 32; m++) {
            int tt = qq + 8 * m;
            S += s_s[tt * 4 + comp];
            Q += s_q[tt * 4 + comp];
        }
        atomicAdd(&g_ssum[layer * 32 + t], S);
        atomicAdd(&g_ssq [layer * 32 + t], Q);
    }
    __threadfence();
    __syncthreads();
    if (t == 0) {
        int v = atomicAdd(&g_cnt[layer], 1);
        last = (v == (int)gridDim.x - 1);
    }
    __syncthreads();
    if (last && t < 32) {
        float sum = atomicAdd(&g_ssum[layer * 32 + t], 0.f);
        float sq  = atomicAdd(&g_ssq [layer * 32 + t], 0.f);
        float mean = sum / (float)NN;
        float var  = sq / (float)NN - mean * mean;
        float a = gg[t] * rsqrtf(var + EPSB);
        g_bnA[t] = a;
        g_bnB[t] = bt[t] - mean * a;
    }
}

// ============ FC0 + fused FC tail in last block ============
#define FCROWS 782   // ceil(1.6M / 2048)
__global__ __launch_bounds__(256) void k_fc0(const float* __restrict__ W0,
                                             const float* __restrict__ fb0,
                                             const float* __restrict__ fW1, const float* __restrict__ fb1,
                                             const float* __restrict__ fW2, const float* __restrict__ fb2,
                                             const float* __restrict__ fW3, const float* __restrict__ fb3,
                                             float* __restrict__ out) {
    __shared__ float s_acc[8 * 128];
    __shared__ bool last;
    int wid = threadIdx.x >> 5, lane = threadIdx.x & 31;
    int k0 = blockIdx.x * FCROWS;
    int k1 = k0 + FCROWS; if (k1 > NN * 32) k1 = NN * 32;
    float a0 = 0.f, a1 = 0.f, a2 = 0.f, a3 = 0.f;
#pragma unroll 4
    for (int k = k0 + wid; k < k1; k += 8) {
        float xk = g_y[k] * g_bnA[k & 31] + g_bnB[k & 31];
        float4 wv = __ldg((const float4*)(W0 + (size_t)k * 128 + 4 * lane));
        a0 += xk * wv.x; a1 += xk * wv.y; a2 += xk * wv.z; a3 += xk * wv.w;
    }
    s_acc[wid * 128 + 4 * lane + 0] = a0;
    s_acc[wid * 128 + 4 * lane + 1] = a1;
    s_acc[wid * 128 + 4 * lane + 2] = a2;
    s_acc[wid * 128 + 4 * lane + 3] = a3;
    __syncthreads();
    int t = threadIdx.x;
    if (t < 128) {
        float s = 0.f;
#pragma unroll
        for (int w = 0; w < 8; w++) s += s_acc[w * 128 + t];
        atomicAdd(&g_fc0[t], s);
    }
    __threadfence();
    __syncthreads();
    if (t == 0) {
        int v = atomicAdd(&g_cntf, 1);
        last = (v == (int)gridDim.x - 1);
    }
    __syncthreads();
    if (last) {
        if (t < 128) s_acc[t] = lrelu(atomicAdd(&g_fc0[t], 0.f) + fb0[t]);
        __syncthreads();
        if (t < 64) {
            float a = fb1[t];
#pragma unroll 8
            for (int k = 0; k < 128; k++) a += s_acc[k] * fW1[k * 64 + t];
            s_acc[256 + t] = lrelu(a);
        }
        __syncthreads();
        if (t < 32) {
            float a = fb2[t];
#pragma unroll 8
            for (int k = 0; k < 64; k++) a += s_acc[256 + k] * fW2[k * 32 + t];
            s_acc[384 + t] = lrelu(a);
        }
        __syncthreads();
        if (t == 0) {
            float a = fb3[0];
#pragma unroll
            for (int k = 0; k < 32; k++) a += s_acc[384 + k] * fW3[k];
            out[0] = a;
        }
    }
}

extern "C" void kernel_launch(void* const* d_in, const int* in_sizes, int n_in,
                              void* d_out, int out_size) {
    const void*  ei  = d_in[0];
    const float* emb = (const float*)d_in[1];
    const float* cb[3] = {(const float*)d_in[3], (const float*)d_in[7], (const float*)d_in[11]};
    const float* gg[3] = {(const float*)d_in[4], (const float*)d_in[8], (const float*)d_in[12]};
    const float* bt[3] = {(const float*)d_in[5], (const float*)d_in[9], (const float*)d_in[13]};
    float* out = (float*)d_out;

    // weights -> constant memory (D2D, graph-capturable memcpy nodes)
    cudaMemcpyToSymbolAsync(c_W0, d_in[2],  128 * 32 * 4, 0, cudaMemcpyDeviceToDevice, 0);
    cudaMemcpyToSymbolAsync(c_W1, d_in[6],   32 * 32 * 4, 0, cudaMemcpyDeviceToDevice, 0);
    cudaMemcpyToSymbolAsync(c_W2, d_in[10],  32 * 32 * 4, 0, cudaMemcpyDeviceToDevice, 0);

    k_prep<<<NBLK, TP>>>(ei);

    k_xw128<<<(NN + 255) / 256, 256>>>(emb);
    k_gather<<<(NN * 8 + 255) / 256, 256>>>(0, cb[0], gg[0], bt[0]);

    k_xw32<1><<<(NN + 255) / 256, 256>>>();
    k_gather<<<(NN * 8 + 255) / 256, 256>>>(1, cb[1], gg[1], bt[1]);

    k_xw32<2><<<(NN + 255) / 256, 256>>>();
    k_gather<<<(NN * 8 + 255) / 256, 256>>>(2, cb[2], gg[2], bt[2]);

    k_fc0<<<2048, 256>>>((const float*)d_in[14], (const float*)d_in[15],
                         (const float*)d_in[16], (const float*)d_in[17],
                         (const float*)d_in[18], (const float*)d_in[19],
                         (const float*)d_in[20], (const float*)d_in[21],
                         out);
    (void)in_sizes; (void)n_in; (void)out_size;
}